// round 8
// baseline (speedup 1.0000x reference)
#include <cuda_runtime.h>
#include <cuda_fp16.h>
#include <cstdint>
#include <limits.h>

#define N_NODES 50000
#define N_EDGES 800000
#define IN_DIM  256
#define HID     128
#define LEAKY   0.01f
#define NEG_INF __int_as_float(0xff800000)
#define SPLIT_TILE 196
#define SPLIT_NODE (SPLIT_TILE * 128)   // 25088

// ---------------- scratch (device globals; device-side use ONLY) -------------
__device__ __align__(16) __half2   g_zh[N_NODES * 64];  // z in fp16 (gather payload)
__device__ __align__(16) float     g_h1[N_NODES * HID]; // layer-1 out (ELU, tf32-rounded)
__device__ __align__(16) uint32_t  g_W1r[HID * IN_DIM]; // tf32-rounded W1
__device__ __align__(16) uint32_t  g_W2r[HID * HID];    // tf32-rounded W2
__device__ float g_ssrc[N_NODES];
__device__ float g_sdst[N_NODES];
__device__ int   g_cnt[N_NODES];
__device__ int   g_off[N_NODES + 1];
__device__ int   g_cur[N_NODES];
__device__ int   g_esrc[N_EDGES];      // CSR (by dst) -> src node id

// ---------------- small helpers ----------------------------------------------
__device__ __forceinline__ uint32_t smem_u32(const void* p) {
    uint32_t a;
    asm("{ .reg .u64 t; cvta.to.shared.u64 t, %1; cvt.u32.u64 %0, t; }" : "=r"(a) : "l"(p));
    return a;
}
__device__ __forceinline__ uint32_t tf32r(float x) {
    uint32_t u;
    asm("cvt.rn.tf32.f32 %0, %1;" : "=r"(u) : "f"(x));
    return u;
}
__device__ __forceinline__ uint32_t tf32r_u(uint32_t v) {
    uint32_t o;
    asm("cvt.rn.tf32.f32 %0, %1;" : "=r"(o) : "f"(__uint_as_float(v)));
    return o;
}
__device__ __forceinline__ void cp16z(uint32_t dst, const void* src, bool valid) {
    int sz = valid ? 16 : 0;
    asm volatile("cp.async.cg.shared.global [%0], [%1], 16, %2;"
                 :: "r"(dst), "l"(src), "r"(sz));
}
__device__ __forceinline__ void cp16(uint32_t dst, const void* src) {
    asm volatile("cp.async.cg.shared.global [%0], [%1], 16;" :: "r"(dst), "l"(src));
}
#define CP_COMMIT() asm volatile("cp.async.commit_group;" ::: "memory")
#define CP_WAIT(N)  asm volatile("cp.async.wait_group %0;" :: "n"(N) : "memory")

__device__ __forceinline__ void mma_tf32(float* c, const uint32_t* a, const uint32_t* b) {
    asm volatile(
        "mma.sync.aligned.m16n8k8.row.col.f32.tf32.tf32.f32 "
        "{%0,%1,%2,%3}, {%4,%5,%6,%7}, {%8,%9}, {%0,%1,%2,%3};"
        : "+f"(c[0]), "+f"(c[1]), "+f"(c[2]), "+f"(c[3])
        : "r"(a[0]), "r"(a[1]), "r"(a[2]), "r"(a[3]), "r"(b[0]), "r"(b[1]));
}

// ---------------- CSR build --------------------------------------------------
__global__ void zero_cnt_kernel() {
    int i = blockIdx.x * blockDim.x + threadIdx.x;
    if (i < N_NODES) g_cnt[i] = 0;
}
__global__ void hist_kernel(const int* __restrict__ dst) {
    int i = blockIdx.x * blockDim.x + threadIdx.x;
    if (i * 4 < N_EDGES) {
        int4 d = ((const int4*)dst)[i];
        atomicAdd(&g_cnt[d.x], 1);
        atomicAdd(&g_cnt[d.y], 1);
        atomicAdd(&g_cnt[d.z], 1);
        atomicAdd(&g_cnt[d.w], 1);
    }
}
__global__ void scan_kernel() {
    __shared__ int sums[1024];
    int tid = threadIdx.x;
    const int chunk = (N_NODES + 1023) / 1024;
    int begin = tid * chunk;
    int end   = begin + chunk; if (end > N_NODES) end = N_NODES;
    if (begin > N_NODES) begin = N_NODES;
    int s = 0;
    for (int i = begin; i < end; ++i) s += g_cnt[i];
    sums[tid] = s;
    __syncthreads();
    for (int off = 1; off < 1024; off <<= 1) {
        int add = 0;
        if (tid >= off) add = sums[tid - off];
        __syncthreads();
        sums[tid] += add;
        __syncthreads();
    }
    int prefix = (tid == 0) ? 0 : sums[tid - 1];
    for (int i = begin; i < end; ++i) {
        g_off[i] = prefix;
        g_cur[i] = prefix;
        prefix += g_cnt[i];
    }
    if (tid == 0) g_off[N_NODES] = sums[1023];
}
__global__ void fill_kernel(const int* __restrict__ dst,
                            const int* __restrict__ src) {
    int i = blockIdx.x * blockDim.x + threadIdx.x;
    if (i * 4 < N_EDGES) {
        int4 d = ((const int4*)dst)[i];
        int4 s = ((const int4*)src)[i];
        int p0 = atomicAdd(&g_cur[d.x], 1);
        int p1 = atomicAdd(&g_cur[d.y], 1);
        int p2 = atomicAdd(&g_cur[d.z], 1);
        int p3 = atomicAdd(&g_cur[d.w], 1);
        g_esrc[p0] = s.x;
        g_esrc[p1] = s.y;
        g_esrc[p2] = s.z;
        g_esrc[p3] = s.w;
    }
}

// ---------------- W pre-round to tf32 ----------------------------------------
__global__ void round_w_kernel(const float* __restrict__ W1,
                               const float* __restrict__ W2) {
    int i = blockIdx.x * blockDim.x + threadIdx.x;
    if (i < HID * IN_DIM) g_W1r[i] = tf32r(W1[i]);
    if (i < HID * HID)    g_W2r[i] = tf32r(W2[i]);
}

// ---------------- cp.async double-buffered tf32 GEMM -------------------------
// z(fp16) = A @ W^T + bias; fused attention dots -> g_ssrc / g_sdst.
// BM=128, BN=128, BK=32; 256 threads = 8 warps; warp tile 32x64.
#define GEMM_SMEM (4 * 18432 + 1024)

template <int K, bool L1>
__global__ __launch_bounds__(256) void gemm_mma(
    const float* __restrict__ Aext, const float* __restrict__ bias,
    const float* __restrict__ avec, int m_base)
{
    const float*    __restrict__ A  = L1 ? Aext : (const float*)g_h1;
    const uint32_t* __restrict__ Wr = L1 ? g_W1r : g_W2r;

    extern __shared__ __align__(16) char dsm[];
    uint32_t* sAb = (uint32_t*)dsm;                    // 2 stages x 4608 words
    uint32_t* sWb = (uint32_t*)(dsm + 2 * 18432);
    float*    sSS = (float*)(dsm + 4 * 18432);
    float*    sSD = sSS + 128;
    uint32_t  smA = smem_u32(sAb), smW = smem_u32(sWb);

    int tid  = threadIdx.x;
    int wid  = tid >> 5, lane = tid & 31;
    int wr   = wid & 3;
    int wc   = wid >> 2;
    int g4   = lane >> 2;
    int q4   = lane & 3;
    int m0   = m_base + blockIdx.x * 128;

    float acc[2][8][4];
#pragma unroll
    for (int mt = 0; mt < 2; ++mt)
#pragma unroll
        for (int nt = 0; nt < 8; ++nt)
#pragma unroll
            for (int j = 0; j < 4; ++j) acc[mt][nt][j] = 0.f;

    const int NT = K / 32;

    auto load_tile = [&](int t, int stage) {
        int k0 = t * 32;
#pragma unroll
        for (int x = tid; x < 1024; x += 256) {
            int row = x >> 3, q = x & 7;
            int gr = m0 + row;
            uint32_t dA = smA + stage * 18432 + (row * 36 + q * 4) * 4;
            cp16z(dA, &((const float4*)A)[(size_t)gr * (K / 4) + (k0 >> 2) + q],
                  gr < N_NODES);
            uint32_t dW = smW + stage * 18432 + (row * 36 + q * 4) * 4;
            cp16(dW, &((const float4*)Wr)[(size_t)row * (K / 4) + (k0 >> 2) + q]);
        }
        CP_COMMIT();
    };

    load_tile(0, 0);
    for (int t = 0; t < NT; ++t) {
        int cur = t & 1;
        if (t + 1 < NT) { load_tile(t + 1, (t + 1) & 1); CP_WAIT(1); }
        else            { CP_WAIT(0); }
        __syncthreads();

        const uint32_t* Ab = sAb + cur * 4608;
        const uint32_t* Wb = sWb + cur * 4608;
#pragma unroll
        for (int kk = 0; kk < 32; kk += 8) {
            uint32_t afr[2][4];
#pragma unroll
            for (int mt = 0; mt < 2; ++mt) {
                int rb = wr * 32 + mt * 16;
                afr[mt][0] = Ab[(rb + g4) * 36 + kk + q4];
                afr[mt][1] = Ab[(rb + 8 + g4) * 36 + kk + q4];
                afr[mt][2] = Ab[(rb + g4) * 36 + kk + 4 + q4];
                afr[mt][3] = Ab[(rb + 8 + g4) * 36 + kk + 4 + q4];
                if (L1) {
#pragma unroll
                    for (int j = 0; j < 4; ++j) afr[mt][j] = tf32r_u(afr[mt][j]);
                }
            }
#pragma unroll
            for (int nt = 0; nt < 8; ++nt) {
                int cb = wc * 64 + nt * 8;
                uint32_t bfr[2];
                bfr[0] = Wb[(cb + g4) * 36 + kk + q4];
                bfr[1] = Wb[(cb + g4) * 36 + kk + 4 + q4];
#pragma unroll
                for (int mt = 0; mt < 2; ++mt)
                    mma_tf32(acc[mt][nt], afr[mt], bfr);
            }
        }
        __syncthreads();
    }

    if (tid < 128) { sSS[tid] = 0.f; sSD[tid] = 0.f; }
    __syncthreads();

    // epilogue: + bias, store z (fp16), accumulate attention dots (fp32)
#pragma unroll
    for (int mt = 0; mt < 2; ++mt) {
        float ss0 = 0.f, sd0 = 0.f, ss1 = 0.f, sd1 = 0.f;
        int r0 = m0 + wr * 32 + mt * 16 + g4;
        int r1 = r0 + 8;
#pragma unroll
        for (int nt = 0; nt < 8; ++nt) {
            int cb = wc * 64 + nt * 8 + q4 * 2;
            float bx = __ldg(&bias[cb]), by = __ldg(&bias[cb + 1]);
            float asx = __ldg(&avec[cb]),       asy = __ldg(&avec[cb + 1]);
            float adx = __ldg(&avec[128 + cb]), ady = __ldg(&avec[128 + cb + 1]);
            float v0 = acc[mt][nt][0] + bx, v1 = acc[mt][nt][1] + by;
            float v2 = acc[mt][nt][2] + bx, v3 = acc[mt][nt][3] + by;
            ss0 += v0 * asx + v1 * asy;
            sd0 += v0 * adx + v1 * ady;
            ss1 += v2 * asx + v3 * asy;
            sd1 += v2 * adx + v3 * ady;
            if (r0 < N_NODES)
                g_zh[(size_t)r0 * 64 + (cb >> 1)] = __float22half2_rn(make_float2(v0, v1));
            if (r1 < N_NODES)
                g_zh[(size_t)r1 * 64 + (cb >> 1)] = __float22half2_rn(make_float2(v2, v3));
        }
        int lr0 = wr * 32 + mt * 16 + g4;
        atomicAdd(&sSS[lr0], ss0);
        atomicAdd(&sSD[lr0], sd0);
        atomicAdd(&sSS[lr0 + 8], ss1);
        atomicAdd(&sSD[lr0 + 8], sd1);
    }
    __syncthreads();
    if (tid < 128 && m0 + tid < N_NODES) {
        g_ssrc[m0 + tid] = sSS[tid];
        g_sdst[m0 + tid] = sSD[tid];
    }
}

// ---------------- fused softmax + weighted aggregation + ELU ----------------
// gathers fp16 z rows; fp32 accumulate. ToExt=false writes g_h1 (tf32-rounded).
template <bool ToExt>
__global__ __launch_bounds__(256) void agg_kernel(const float* __restrict__ ab_ptr,
                                                  float* __restrict__ out_ext,
                                                  int node_base, int node_end)
{
    __shared__ float sWgt[8][128];
    __shared__ int   sSrc[8][128];
    float* __restrict__ out = ToExt ? out_ext : (float*)g_h1;
    int gt    = blockIdx.x * blockDim.x + threadIdx.x;
    int node  = node_base + (gt >> 5);
    int lane  = gt & 31;
    int wslot = (threadIdx.x >> 5);
    if (node >= node_end) return;
    int beg = g_off[node], end = g_off[node + 1], deg = end - beg;
    float sdn = g_sdst[node] + ab_ptr[0];

    float ev[4]; int snv[4];
    float m = NEG_INF;
#pragma unroll
    for (int l = 0; l < 4; ++l) {
        int s = beg + lane + l * 32;
        float e = NEG_INF; int sn = 0;
        if (s < end) {
            sn = g_esrc[s];
            e = g_ssrc[sn] + sdn;
            e = (e > 0.f) ? e : LEAKY * e;
        }
        ev[l] = e; snv[l] = sn;
        m = fmaxf(m, e);
    }
    for (int s = beg + 128 + lane; s < end; s += 32) {
        float e = g_ssrc[g_esrc[s]] + sdn;
        e = (e > 0.f) ? e : LEAKY * e;
        m = fmaxf(m, e);
    }
#pragma unroll
    for (int o = 16; o > 0; o >>= 1) m = fmaxf(m, __shfl_xor_sync(0xffffffffu, m, o));

    float S = 0.f;
#pragma unroll
    for (int l = 0; l < 4; ++l)
        if (beg + lane + l * 32 < end) S += __expf(ev[l] - m);
    for (int s = beg + 128 + lane; s < end; s += 32) {
        float e = g_ssrc[g_esrc[s]] + sdn;
        e = (e > 0.f) ? e : LEAKY * e;
        S += __expf(e - m);
    }
#pragma unroll
    for (int o = 16; o > 0; o >>= 1) S += __shfl_xor_sync(0xffffffffu, S, o);
    float inv = (deg > 0) ? (1.f / S) : 0.f;

#pragma unroll
    for (int l = 0; l < 4; ++l) {
        int idx = lane + l * 32;
        if (beg + idx < end) {
            sWgt[wslot][idx] = __expf(ev[l] - m) * inv;
            sSrc[wslot][idx] = snv[l];
        }
    }
    __syncwarp();

    float4 acc = make_float4(0.f, 0.f, 0.f, 0.f);
    int nin = deg < 128 ? deg : 128;
#pragma unroll 4
    for (int i = 0; i < nin; ++i) {
        float w  = sWgt[wslot][i];
        int   sn = sSrc[wslot][i];
        uint2 zr = ((const uint2*)g_zh)[(size_t)sn * 32 + lane];
        float2 f0 = __half22float2(*reinterpret_cast<__half2*>(&zr.x));
        float2 f1 = __half22float2(*reinterpret_cast<__half2*>(&zr.y));
        acc.x += w * f0.x; acc.y += w * f0.y;
        acc.z += w * f1.x; acc.w += w * f1.y;
    }
    for (int s = beg + 128; s < end; ++s) {           // rare tail (deg > 128)
        int sn  = g_esrc[s];
        float e = g_ssrc[sn] + sdn;
        e = (e > 0.f) ? e : LEAKY * e;
        float w = __expf(e - m) * inv;
        uint2 zr = ((const uint2*)g_zh)[(size_t)sn * 32 + lane];
        float2 f0 = __half22float2(*reinterpret_cast<__half2*>(&zr.x));
        float2 f1 = __half22float2(*reinterpret_cast<__half2*>(&zr.y));
        acc.x += w * f0.x; acc.y += w * f0.y;
        acc.z += w * f1.x; acc.w += w * f1.y;
    }
    // ELU (alpha = 1)
    acc.x = (acc.x > 0.f) ? acc.x : (__expf(acc.x) - 1.f);
    acc.y = (acc.y > 0.f) ? acc.y : (__expf(acc.y) - 1.f);
    acc.z = (acc.z > 0.f) ? acc.z : (__expf(acc.z) - 1.f);
    acc.w = (acc.w > 0.f) ? acc.w : (__expf(acc.w) - 1.f);
    if (!ToExt) {   // pre-round for GEMM2's tf32 consumption
        acc.x = __uint_as_float(tf32r(acc.x));
        acc.y = __uint_as_float(tf32r(acc.y));
        acc.z = __uint_as_float(tf32r(acc.z));
        acc.w = __uint_as_float(tf32r(acc.w));
    }
    ((float4*)out)[(size_t)node * 32 + lane] = acc;
}

// ---------------- launch ------------------------------------------------------
extern "C" void kernel_launch(void* const* d_in, const int* in_sizes, int n_in,
                              void* d_out, int out_size) {
    const float* h   = (const float*)d_in[0];
    const int*   src = (const int*)d_in[1];
    const int*   dst = (const int*)d_in[2];
    const float* W1  = (const float*)d_in[3];
    const float* b1  = (const float*)d_in[4];
    const float* a1  = (const float*)d_in[5];
    const float* ab1 = (const float*)d_in[6];
    const float* W2  = (const float*)d_in[7];
    const float* b2  = (const float*)d_in[8];
    const float* a2  = (const float*)d_in[9];
    const float* ab2 = (const float*)d_in[10];
    float* out = (float*)d_out;

    const int NB_N  = (N_NODES + 255) / 256;
    const int NB_E4 = (N_EDGES / 4 + 255) / 256;
    const int NB_G  = (N_NODES + 127) / 128;       // 391 tiles
    const int T0    = SPLIT_TILE;                  // 196 tiles -> nodes [0, 25088)
    const int T1    = NB_G - SPLIT_TILE;           // 195 tiles
    const int NBW0  = (SPLIT_NODE + 7) / 8;
    const int NBW1  = (N_NODES - SPLIT_NODE + 7) / 8;
    const int NBW   = (N_NODES + 7) / 8;

    cudaFuncSetAttribute(gemm_mma<IN_DIM, true>,
                         cudaFuncAttributeMaxDynamicSharedMemorySize, GEMM_SMEM);
    cudaFuncSetAttribute(gemm_mma<HID, false>,
                         cudaFuncAttributeMaxDynamicSharedMemorySize, GEMM_SMEM);

    // fork: CSR chain on s2 concurrent with W-round + GEMM1 on main stream
    cudaStream_t s2 = 0;
    cudaEvent_t evFork = nullptr, evCsr = nullptr, evA0 = nullptr, evG20 = nullptr;
    bool forked =
        cudaStreamCreateWithFlags(&s2, cudaStreamNonBlocking) == cudaSuccess &&
        cudaEventCreateWithFlags(&evFork, cudaEventDisableTiming) == cudaSuccess &&
        cudaEventCreateWithFlags(&evCsr, cudaEventDisableTiming) == cudaSuccess &&
        cudaEventCreateWithFlags(&evA0, cudaEventDisableTiming) == cudaSuccess &&
        cudaEventCreateWithFlags(&evG20, cudaEventDisableTiming) == cudaSuccess;
    cudaStream_t cs = forked ? s2 : (cudaStream_t)0;
    if (forked) {
        cudaEventRecord(evFork, 0);
        cudaStreamWaitEvent(s2, evFork, 0);
    }

    zero_cnt_kernel<<<NB_N, 256, 0, cs>>>();
    hist_kernel<<<NB_E4, 256, 0, cs>>>(dst);
    scan_kernel<<<1, 1024, 0, cs>>>();
    fill_kernel<<<NB_E4, 256, 0, cs>>>(dst, src);
    if (forked) cudaEventRecord(evCsr, s2);

    round_w_kernel<<<(HID * IN_DIM + 255) / 256, 256>>>(W1, W2);
    gemm_mma<IN_DIM, true><<<NB_G, 256, GEMM_SMEM>>>(h, b1, a1, 0);

    if (forked) cudaStreamWaitEvent(0, evCsr, 0);

    if (forked) {
        // pipelined: agg1(C0) -> { GEMM2(C0) on s2  ||  agg1(C1) on main }
        agg_kernel<false><<<NBW0, 256>>>(ab1, nullptr, 0, SPLIT_NODE);
        cudaEventRecord(evA0, 0);
        cudaStreamWaitEvent(s2, evA0, 0);
        gemm_mma<HID, false><<<T0, 256, GEMM_SMEM, s2>>>(nullptr, b2, a2, 0);
        cudaEventRecord(evG20, s2);
        agg_kernel<false><<<NBW1, 256>>>(ab1, nullptr, SPLIT_NODE, N_NODES);
        gemm_mma<HID, false><<<T1, 256, GEMM_SMEM>>>(nullptr, b2, a2, SPLIT_NODE);
        cudaStreamWaitEvent(0, evG20, 0);
    } else {
        agg_kernel<false><<<NBW, 256>>>(ab1, nullptr, 0, N_NODES);
        gemm_mma<HID, false><<<NB_G, 256, GEMM_SMEM>>>(nullptr, b2, a2, 0);
    }

    agg_kernel<true><<<NBW, 256>>>(ab2, out, 0, N_NODES);
    // streams/events intentionally leaked: replays run the captured graph only.
}

// round 9
// speedup vs baseline: 1.1978x; 1.1978x over previous
#include <cuda_runtime.h>
#include <cuda_fp16.h>
#include <cstdint>
#include <limits.h>

#define N_NODES 50000
#define N_EDGES 800000
#define IN_DIM  256
#define HID     128
#define LEAKY   0.01f
#define NEG_INF __int_as_float(0xff800000)

// ---------------- scratch (device globals; device-side use ONLY) -------------
__device__ __align__(16) __half2   g_zh[N_NODES * 64];  // z in fp16 (gather payload)
__device__ __align__(16) float     g_h1[N_NODES * HID]; // layer-1 out (ELU, tf32-rounded)
__device__ __align__(16) uint32_t  g_W1r[HID * IN_DIM]; // tf32-rounded W1
__device__ __align__(16) uint32_t  g_W2r[HID * HID];    // tf32-rounded W2
__device__ float g_ssrc[N_NODES];
__device__ float g_sdst[N_NODES];
__device__ int   g_cnt[N_NODES];
__device__ int   g_off[N_NODES + 1];
__device__ int   g_cur[N_NODES];
__device__ int   g_esrc[N_EDGES];      // CSR (by dst) -> src node id

// ---------------- small helpers ----------------------------------------------
__device__ __forceinline__ uint32_t smem_u32(const void* p) {
    uint32_t a;
    asm("{ .reg .u64 t; cvta.to.shared.u64 t, %1; cvt.u32.u64 %0, t; }" : "=r"(a) : "l"(p));
    return a;
}
__device__ __forceinline__ uint32_t tf32r(float x) {
    uint32_t u;
    asm("cvt.rn.tf32.f32 %0, %1;" : "=r"(u) : "f"(x));
    return u;
}
__device__ __forceinline__ uint32_t tf32r_u(uint32_t v) {
    uint32_t o;
    asm("cvt.rn.tf32.f32 %0, %1;" : "=r"(o) : "f"(__uint_as_float(v)));
    return o;
}
__device__ __forceinline__ void cp16z(uint32_t dst, const void* src, bool valid) {
    int sz = valid ? 16 : 0;
    asm volatile("cp.async.cg.shared.global [%0], [%1], 16, %2;"
                 :: "r"(dst), "l"(src), "r"(sz));
}
__device__ __forceinline__ void cp16(uint32_t dst, const void* src) {
    asm volatile("cp.async.cg.shared.global [%0], [%1], 16;" :: "r"(dst), "l"(src));
}
#define CP_COMMIT() asm volatile("cp.async.commit_group;" ::: "memory")
#define CP_WAIT(N)  asm volatile("cp.async.wait_group %0;" :: "n"(N) : "memory")

__device__ __forceinline__ void mma_tf32(float* c, const uint32_t* a, const uint32_t* b) {
    asm volatile(
        "mma.sync.aligned.m16n8k8.row.col.f32.tf32.tf32.f32 "
        "{%0,%1,%2,%3}, {%4,%5,%6,%7}, {%8,%9}, {%0,%1,%2,%3};"
        : "+f"(c[0]), "+f"(c[1]), "+f"(c[2]), "+f"(c[3])
        : "r"(a[0]), "r"(a[1]), "r"(a[2]), "r"(a[3]), "r"(b[0]), "r"(b[1]));
}

// ---------------- CSR build --------------------------------------------------
__global__ void zero_cnt_kernel() {
    int i = blockIdx.x * blockDim.x + threadIdx.x;
    if (i < N_NODES) g_cnt[i] = 0;
}
__global__ void hist_kernel(const int* __restrict__ dst) {
    int i = blockIdx.x * blockDim.x + threadIdx.x;
    if (i * 4 < N_EDGES) {
        int4 d = ((const int4*)dst)[i];
        atomicAdd(&g_cnt[d.x], 1);
        atomicAdd(&g_cnt[d.y], 1);
        atomicAdd(&g_cnt[d.z], 1);
        atomicAdd(&g_cnt[d.w], 1);
    }
}
__global__ void scan_kernel() {
    __shared__ int sums[1024];
    int tid = threadIdx.x;
    const int chunk = (N_NODES + 1023) / 1024;
    int begin = tid * chunk;
    int end   = begin + chunk; if (end > N_NODES) end = N_NODES;
    if (begin > N_NODES) begin = N_NODES;
    int s = 0;
    for (int i = begin; i < end; ++i) s += g_cnt[i];
    sums[tid] = s;
    __syncthreads();
    for (int off = 1; off < 1024; off <<= 1) {
        int add = 0;
        if (tid >= off) add = sums[tid - off];
        __syncthreads();
        sums[tid] += add;
        __syncthreads();
    }
    int prefix = (tid == 0) ? 0 : sums[tid - 1];
    for (int i = begin; i < end; ++i) {
        g_off[i] = prefix;
        g_cur[i] = prefix;
        prefix += g_cnt[i];
    }
    if (tid == 0) g_off[N_NODES] = sums[1023];
}
__global__ void fill_kernel(const int* __restrict__ dst,
                            const int* __restrict__ src) {
    int i = blockIdx.x * blockDim.x + threadIdx.x;
    if (i * 4 < N_EDGES) {
        int4 d = ((const int4*)dst)[i];
        int4 s = ((const int4*)src)[i];
        int p0 = atomicAdd(&g_cur[d.x], 1);
        int p1 = atomicAdd(&g_cur[d.y], 1);
        int p2 = atomicAdd(&g_cur[d.z], 1);
        int p3 = atomicAdd(&g_cur[d.w], 1);
        g_esrc[p0] = s.x;
        g_esrc[p1] = s.y;
        g_esrc[p2] = s.z;
        g_esrc[p3] = s.w;
    }
}

// ---------------- W pre-round to tf32 ----------------------------------------
__global__ void round_w_kernel(const float* __restrict__ W1,
                               const float* __restrict__ W2) {
    int i = blockIdx.x * blockDim.x + threadIdx.x;
    if (i < HID * IN_DIM) g_W1r[i] = tf32r(W1[i]);
    if (i < HID * HID)    g_W2r[i] = tf32r(W2[i]);
}

// ---------------- cp.async double-buffered tf32 GEMM -------------------------
// z(fp16) = A @ W^T + bias; fused attention dots -> g_ssrc / g_sdst.
// BM=128, BN=128, BK=32; 256 threads = 8 warps; warp tile 32x64.
#define GEMM_SMEM (4 * 18432 + 1024)

template <int K, bool L1>
__global__ __launch_bounds__(256) void gemm_mma(
    const float* __restrict__ Aext, const float* __restrict__ bias,
    const float* __restrict__ avec)
{
    const float*    __restrict__ A  = L1 ? Aext : (const float*)g_h1;
    const uint32_t* __restrict__ Wr = L1 ? g_W1r : g_W2r;

    extern __shared__ __align__(16) char dsm[];
    uint32_t* sAb = (uint32_t*)dsm;                    // 2 stages x 4608 words
    uint32_t* sWb = (uint32_t*)(dsm + 2 * 18432);
    float*    sSS = (float*)(dsm + 4 * 18432);
    float*    sSD = sSS + 128;
    uint32_t  smA = smem_u32(sAb), smW = smem_u32(sWb);

    int tid  = threadIdx.x;
    int wid  = tid >> 5, lane = tid & 31;
    int wr   = wid & 3;
    int wc   = wid >> 2;
    int g4   = lane >> 2;
    int q4   = lane & 3;
    int m0   = blockIdx.x * 128;

    float acc[2][8][4];
#pragma unroll
    for (int mt = 0; mt < 2; ++mt)
#pragma unroll
        for (int nt = 0; nt < 8; ++nt)
#pragma unroll
            for (int j = 0; j < 4; ++j) acc[mt][nt][j] = 0.f;

    const int NT = K / 32;

    auto load_tile = [&](int t, int stage) {
        int k0 = t * 32;
#pragma unroll
        for (int x = tid; x < 1024; x += 256) {
            int row = x >> 3, q = x & 7;
            int gr = m0 + row;
            uint32_t dA = smA + stage * 18432 + (row * 36 + q * 4) * 4;
            cp16z(dA, &((const float4*)A)[(size_t)gr * (K / 4) + (k0 >> 2) + q],
                  gr < N_NODES);
            uint32_t dW = smW + stage * 18432 + (row * 36 + q * 4) * 4;
            cp16(dW, &((const float4*)Wr)[(size_t)row * (K / 4) + (k0 >> 2) + q]);
        }
        CP_COMMIT();
    };

    load_tile(0, 0);
    for (int t = 0; t < NT; ++t) {
        int cur = t & 1;
        if (t + 1 < NT) { load_tile(t + 1, (t + 1) & 1); CP_WAIT(1); }
        else            { CP_WAIT(0); }
        __syncthreads();

        const uint32_t* Ab = sAb + cur * 4608;
        const uint32_t* Wb = sWb + cur * 4608;
#pragma unroll
        for (int kk = 0; kk < 32; kk += 8) {
            uint32_t afr[2][4];
#pragma unroll
            for (int mt = 0; mt < 2; ++mt) {
                int rb = wr * 32 + mt * 16;
                afr[mt][0] = Ab[(rb + g4) * 36 + kk + q4];
                afr[mt][1] = Ab[(rb + 8 + g4) * 36 + kk + q4];
                afr[mt][2] = Ab[(rb + g4) * 36 + kk + 4 + q4];
                afr[mt][3] = Ab[(rb + 8 + g4) * 36 + kk + 4 + q4];
                if (L1) {
#pragma unroll
                    for (int j = 0; j < 4; ++j) afr[mt][j] = tf32r_u(afr[mt][j]);
                }
            }
#pragma unroll
            for (int nt = 0; nt < 8; ++nt) {
                int cb = wc * 64 + nt * 8;
                uint32_t bfr[2];
                bfr[0] = Wb[(cb + g4) * 36 + kk + q4];
                bfr[1] = Wb[(cb + g4) * 36 + kk + 4 + q4];
#pragma unroll
                for (int mt = 0; mt < 2; ++mt)
                    mma_tf32(acc[mt][nt], afr[mt], bfr);
            }
        }
        __syncthreads();
    }

    if (tid < 128) { sSS[tid] = 0.f; sSD[tid] = 0.f; }
    __syncthreads();

    // epilogue: + bias, store z (fp16), accumulate attention dots (fp32)
#pragma unroll
    for (int mt = 0; mt < 2; ++mt) {
        float ss0 = 0.f, sd0 = 0.f, ss1 = 0.f, sd1 = 0.f;
        int r0 = m0 + wr * 32 + mt * 16 + g4;
        int r1 = r0 + 8;
#pragma unroll
        for (int nt = 0; nt < 8; ++nt) {
            int cb = wc * 64 + nt * 8 + q4 * 2;
            float bx = __ldg(&bias[cb]), by = __ldg(&bias[cb + 1]);
            float asx = __ldg(&avec[cb]),       asy = __ldg(&avec[cb + 1]);
            float adx = __ldg(&avec[128 + cb]), ady = __ldg(&avec[128 + cb + 1]);
            float v0 = acc[mt][nt][0] + bx, v1 = acc[mt][nt][1] + by;
            float v2 = acc[mt][nt][2] + bx, v3 = acc[mt][nt][3] + by;
            ss0 += v0 * asx + v1 * asy;
            sd0 += v0 * adx + v1 * ady;
            ss1 += v2 * asx + v3 * asy;
            sd1 += v2 * adx + v3 * ady;
            if (r0 < N_NODES)
                g_zh[(size_t)r0 * 64 + (cb >> 1)] = __float22half2_rn(make_float2(v0, v1));
            if (r1 < N_NODES)
                g_zh[(size_t)r1 * 64 + (cb >> 1)] = __float22half2_rn(make_float2(v2, v3));
        }
        int lr0 = wr * 32 + mt * 16 + g4;
        atomicAdd(&sSS[lr0], ss0);
        atomicAdd(&sSD[lr0], sd0);
        atomicAdd(&sSS[lr0 + 8], ss1);
        atomicAdd(&sSD[lr0 + 8], sd1);
    }
    __syncthreads();
    if (tid < 128 && m0 + tid < N_NODES) {
        g_ssrc[m0 + tid] = sSS[tid];
        g_sdst[m0 + tid] = sSD[tid];
    }
}

// ---------------- fused softmax + weighted aggregation + ELU ----------------
// gathers fp16 z rows; fp32 accumulate. ToExt=false writes g_h1 (tf32-rounded).
template <bool ToExt>
__global__ __launch_bounds__(256) void agg_kernel(const float* __restrict__ ab_ptr,
                                                  float* __restrict__ out_ext)
{
    __shared__ float sWgt[8][128];
    __shared__ int   sSrc[8][128];
    float* __restrict__ out = ToExt ? out_ext : (float*)g_h1;
    int gt    = blockIdx.x * blockDim.x + threadIdx.x;
    int node  = gt >> 5;
    int lane  = gt & 31;
    int wslot = (threadIdx.x >> 5);
    if (node >= N_NODES) return;
    int beg = g_off[node], end = g_off[node + 1], deg = end - beg;
    float sdn = g_sdst[node] + ab_ptr[0];

    float ev[4]; int snv[4];
    float m = NEG_INF;
#pragma unroll
    for (int l = 0; l < 4; ++l) {
        int s = beg + lane + l * 32;
        float e = NEG_INF; int sn = 0;
        if (s < end) {
            sn = g_esrc[s];
            e = g_ssrc[sn] + sdn;
            e = (e > 0.f) ? e : LEAKY * e;
        }
        ev[l] = e; snv[l] = sn;
        m = fmaxf(m, e);
    }
    for (int s = beg + 128 + lane; s < end; s += 32) {
        float e = g_ssrc[g_esrc[s]] + sdn;
        e = (e > 0.f) ? e : LEAKY * e;
        m = fmaxf(m, e);
    }
#pragma unroll
    for (int o = 16; o > 0; o >>= 1) m = fmaxf(m, __shfl_xor_sync(0xffffffffu, m, o));

    float S = 0.f;
#pragma unroll
    for (int l = 0; l < 4; ++l)
        if (beg + lane + l * 32 < end) S += __expf(ev[l] - m);
    for (int s = beg + 128 + lane; s < end; s += 32) {
        float e = g_ssrc[g_esrc[s]] + sdn;
        e = (e > 0.f) ? e : LEAKY * e;
        S += __expf(e - m);
    }
#pragma unroll
    for (int o = 16; o > 0; o >>= 1) S += __shfl_xor_sync(0xffffffffu, S, o);
    float inv = (deg > 0) ? (1.f / S) : 0.f;

#pragma unroll
    for (int l = 0; l < 4; ++l) {
        int idx = lane + l * 32;
        if (beg + idx < end) {
            sWgt[wslot][idx] = __expf(ev[l] - m) * inv;
            sSrc[wslot][idx] = snv[l];
        }
    }
    __syncwarp();

    float4 acc = make_float4(0.f, 0.f, 0.f, 0.f);
    int nin = deg < 128 ? deg : 128;
#pragma unroll 4
    for (int i = 0; i < nin; ++i) {
        float w  = sWgt[wslot][i];
        int   sn = sSrc[wslot][i];
        uint2 zr = ((const uint2*)g_zh)[(size_t)sn * 32 + lane];
        float2 f0 = __half22float2(*reinterpret_cast<__half2*>(&zr.x));
        float2 f1 = __half22float2(*reinterpret_cast<__half2*>(&zr.y));
        acc.x += w * f0.x; acc.y += w * f0.y;
        acc.z += w * f1.x; acc.w += w * f1.y;
    }
    for (int s = beg + 128; s < end; ++s) {           // rare tail (deg > 128)
        int sn  = g_esrc[s];
        float e = g_ssrc[sn] + sdn;
        e = (e > 0.f) ? e : LEAKY * e;
        float w = __expf(e - m) * inv;
        uint2 zr = ((const uint2*)g_zh)[(size_t)sn * 32 + lane];
        float2 f0 = __half22float2(*reinterpret_cast<__half2*>(&zr.x));
        float2 f1 = __half22float2(*reinterpret_cast<__half2*>(&zr.y));
        acc.x += w * f0.x; acc.y += w * f0.y;
        acc.z += w * f1.x; acc.w += w * f1.y;
    }
    // ELU (alpha = 1)
    acc.x = (acc.x > 0.f) ? acc.x : (__expf(acc.x) - 1.f);
    acc.y = (acc.y > 0.f) ? acc.y : (__expf(acc.y) - 1.f);
    acc.z = (acc.z > 0.f) ? acc.z : (__expf(acc.z) - 1.f);
    acc.w = (acc.w > 0.f) ? acc.w : (__expf(acc.w) - 1.f);
    if (!ToExt) {   // pre-round for GEMM2's tf32 consumption
        acc.x = __uint_as_float(tf32r(acc.x));
        acc.y = __uint_as_float(tf32r(acc.y));
        acc.z = __uint_as_float(tf32r(acc.z));
        acc.w = __uint_as_float(tf32r(acc.w));
    }
    ((float4*)out)[(size_t)node * 32 + lane] = acc;
}

// ---------------- launch ------------------------------------------------------
extern "C" void kernel_launch(void* const* d_in, const int* in_sizes, int n_in,
                              void* d_out, int out_size) {
    const float* h   = (const float*)d_in[0];
    const int*   src = (const int*)d_in[1];
    const int*   dst = (const int*)d_in[2];
    const float* W1  = (const float*)d_in[3];
    const float* b1  = (const float*)d_in[4];
    const float* a1  = (const float*)d_in[5];
    const float* ab1 = (const float*)d_in[6];
    const float* W2  = (const float*)d_in[7];
    const float* b2  = (const float*)d_in[8];
    const float* a2  = (const float*)d_in[9];
    const float* ab2 = (const float*)d_in[10];
    float* out = (float*)d_out;

    const int NB_N  = (N_NODES + 255) / 256;
    const int NB_E4 = (N_EDGES / 4 + 255) / 256;
    const int NB_W  = (N_NODES + 7) / 8;
    const int NB_G  = (N_NODES + 127) / 128;   // 391 tiles

    cudaFuncSetAttribute(gemm_mma<IN_DIM, true>,
                         cudaFuncAttributeMaxDynamicSharedMemorySize, GEMM_SMEM);
    cudaFuncSetAttribute(gemm_mma<HID, false>,
                         cudaFuncAttributeMaxDynamicSharedMemorySize, GEMM_SMEM);

    // fork: CSR chain on s2 concurrent with W-round + GEMM1 on main stream
    cudaStream_t s2 = 0;
    cudaEvent_t evFork = nullptr, evCsr = nullptr;
    bool forked =
        cudaStreamCreateWithFlags(&s2, cudaStreamNonBlocking) == cudaSuccess &&
        cudaEventCreateWithFlags(&evFork, cudaEventDisableTiming) == cudaSuccess &&
        cudaEventCreateWithFlags(&evCsr, cudaEventDisableTiming) == cudaSuccess;
    cudaStream_t cs = forked ? s2 : (cudaStream_t)0;
    if (forked) {
        cudaEventRecord(evFork, 0);
        cudaStreamWaitEvent(s2, evFork, 0);
    }

    zero_cnt_kernel<<<NB_N, 256, 0, cs>>>();
    hist_kernel<<<NB_E4, 256, 0, cs>>>(dst);
    scan_kernel<<<1, 1024, 0, cs>>>();
    fill_kernel<<<NB_E4, 256, 0, cs>>>(dst, src);
    if (forked) cudaEventRecord(evCsr, s2);

    round_w_kernel<<<(HID * IN_DIM + 255) / 256, 256>>>(W1, W2);
    gemm_mma<IN_DIM, true><<<NB_G, 256, GEMM_SMEM>>>(h, b1, a1);

    if (forked) cudaStreamWaitEvent(0, evCsr, 0);
    agg_kernel<false><<<NB_W, 256>>>(ab1, nullptr);

    gemm_mma<HID, false><<<NB_G, 256, GEMM_SMEM>>>(nullptr, b2, a2);
    agg_kernel<true><<<NB_W, 256>>>(ab2, out);
    // streams/events intentionally leaked: replays run the captured graph only.
}